// round 9
// baseline (speedup 1.0000x reference)
#include <cuda_runtime.h>

#define TLEN  1024
#define BATCH 64
#define NTH   256               // 8 warps = 2 per SMSP
#define RPT   4                 // rows per thread (NTH*RPT == TLEN)
#define NPG   128               // column groups of 8 cols (4 pairs) per step
#define NSTEP (NPG + NTH - 1)   // 383
#define INFV  1e30f

__device__ float g_losses[BATCH];
__device__ unsigned int g_done = 0;   // self-resetting ticket (wraps at BATCH)

__device__ __forceinline__ float sqrt_approx(float x) {
    float r; asm("sqrt.approx.f32 %0, %1;" : "=f"(r) : "f"(x)); return r;
}

// One block per batch. Thread t owns rows 4t..4t+3. At step s it processes
// column group k = s - t (8 columns = 4 pairs): a 4x8 register tile.
// Cross-thread dep: bottom row of thread t-1 over those 8 columns,
// double-buffered in shared as 4 float4 planes (conflict-free stride).
// DP carried:
//   C[i,j] = D(i,j) + min(diag, up, left)
//   L[i,j] = L1w(i,j) + L[parent], parent = first-min in order (diag, up,
// left) == reference backtrace rule, so loss = L[T-1,T-1] (no backtrace).
__global__ void __launch_bounds__(NTH, 1)
dtw_kernel(const float* __restrict__ preds, const float* __restrict__ targs,
           const float* __restrict__ subcoef, float* __restrict__ out)
{
    __shared__ float4 qs4[4][NPG];        // quad i of group g: cols 8g+2i, 8g+2i+1
    __shared__ float4 bnd[2][4][NTH + 1]; // boundary planes, ghost slot 0

    const int b = blockIdx.x;
    const int t = threadIdx.x;
    const float* P = preds + (size_t)b * TLEN * 4;
    const float* Q = targs + (size_t)b * TLEN * 4;

    for (int k = t; k < TLEN / 2; k += NTH) {      // pair k = cols 2k, 2k+1
        float4 a = *(const float4*)(Q + 8 * k);
        float4 c = *(const float4*)(Q + 8 * k + 4);
        qs4[k & 3][k >> 2] = make_float4(a.x, a.y, c.x, c.y);
    }
    float px[RPT], py[RPT];
    const int rb = t * RPT;
#pragma unroll
    for (int r = 0; r < RPT; r++) {
        px[r] = P[(rb + r) * 4 + 0];
        py[r] = P[(rb + r) * 4 + 1];
    }
    const float sc0 = subcoef[0], sc1 = subcoef[1];

    if (t == 0) {                          // constant top boundary (both parities)
        float4 inf4 = make_float4(INFV, 0.f, INFV, 0.f);
#pragma unroll
        for (int i = 0; i < 4; i++) { bnd[0][i][0] = inf4; bnd[1][i][0] = inf4; }
    }

    float Cl[RPT], Ll[RPT];                // own rows at col c-1
#pragma unroll
    for (int r = 0; r < RPT; r++) { Cl[r] = INFV; Ll[r] = 0.f; }
    float bCp = INFV, bLp = 0.f;           // t-1 bottom at first col - 1 (diag lag)

    __syncthreads();

    for (int s = 0; s < NSTEP; ++s) {
        const int k  = s - t;
        const int Pw = s & 1;
        if (k >= 0 && k < NPG) {
            const bool orig = (t == 0) && (k == 0);
            float dgC = bCp, dgL = bLp;

#pragma unroll
            for (int i = 0; i < 4; i++) {          // 4 column pairs
                const float4 bq = bnd[Pw ^ 1][i][t];   // t-1 bottom @ {c0, c1}
                const float4 q  = qs4[i][k];

                float A[RPT], LA[RPT];             // column c0 = 8k+2i
                {
                    float dg = dgC, dgl = dgL, up = bq.x, upl = bq.y;
#pragma unroll
                    for (int r = 0; r < RPT; r++) {
                        const float dx = px[r] - q.x, dy = py[r] - q.y;
                        const float D  = sqrt_approx(fmaf(dx, dx, dy * dy));
                        const float m1  = fminf(dg, up);
                        const float m1l = (dg <= up) ? dgl : upl;
                        float m  = fminf(m1, Cl[r]);
                        float Lp = (m1 <= Cl[r]) ? m1l : Ll[r];
                        if (i == 0 && r == 0 && orig) { m = 0.f; Lp = 0.f; }
                        A[r]  = D + m;
                        LA[r] = fmaf(fabsf(dx), sc0, fmaf(fabsf(dy), sc1, Lp));
                        dg = Cl[r]; dgl = Ll[r];
                        up = A[r];  upl = LA[r];
                    }
                }
                float Bv[RPT], LB[RPT];            // column c1 = 8k+2i+1
                {
                    float dg = bq.x, dgl = bq.y, up = bq.z, upl = bq.w;
#pragma unroll
                    for (int r = 0; r < RPT; r++) {
                        const float dx = px[r] - q.z, dy = py[r] - q.w;
                        const float D  = sqrt_approx(fmaf(dx, dx, dy * dy));
                        const float m1  = fminf(dg, up);
                        const float m1l = (dg <= up) ? dgl : upl;
                        const float m  = fminf(m1, A[r]);
                        const float Lp = (m1 <= A[r]) ? m1l : LA[r];
                        Bv[r] = D + m;
                        LB[r] = fmaf(fabsf(dx), sc0, fmaf(fabsf(dy), sc1, Lp));
                        dg = A[r];  dgl = LA[r];
                        up = Bv[r]; upl = LB[r];
                    }
                }
#pragma unroll
                for (int r = 0; r < RPT; r++) { Cl[r] = Bv[r]; Ll[r] = LB[r]; }
                dgC = bq.z; dgL = bq.w;            // diag for next pair's c0

                bnd[Pw][i][t + 1] =
                    make_float4(A[RPT-1], LA[RPT-1], Bv[RPT-1], LB[RPT-1]);

                if (t == NTH - 1 && k == NPG - 1 && i == 3)   // cell (1023,1023)
                    g_losses[b] = LB[RPT - 1];
            }
            bCp = dgC; bLp = dgL;                  // boundary diag lag across steps
        }
        __syncthreads();
    }

    // Last block sums all batch losses in fixed order (deterministic).
    if (t == NTH - 1) {
        __threadfence();
        unsigned int old = atomicInc(&g_done, BATCH - 1);  // wraps -> self-reset
        if (old == BATCH - 1) {
            __threadfence();
            float sum = 0.f;
#pragma unroll
            for (int i = 0; i < BATCH; i++) sum += __ldcg(&g_losses[i]);
            out[0] = sum;
        }
    }
}

extern "C" void kernel_launch(void* const* d_in, const int* in_sizes, int n_in,
                              void* d_out, int out_size)
{
    const float* preds   = (const float*)d_in[0];
    const float* targs   = (const float*)d_in[1];
    const float* subcoef = (const float*)d_in[2];
    float* out = (float*)d_out;
    (void)in_sizes; (void)n_in; (void)out_size;

    dtw_kernel<<<BATCH, NTH>>>(preds, targs, subcoef, out);
}